// round 17
// baseline (speedup 1.0000x reference)
#include <cuda_runtime.h>
#include <math.h>

typedef unsigned long long ull;

// Problem constants
#define Bk   4
#define Ck   256
#define BNk  64
#define Hk   128
#define Wk   128
#define HWk  16384
#define K2k  9

// -------- packed f32x2 helpers (Blackwell FFMA2) --------
__device__ __forceinline__ void ffma2(ull& d, ull a, ull b) {
    asm("fma.rn.f32x2 %0, %1, %2, %0;" : "+l"(d) : "l"(a), "l"(b));
}
__device__ __forceinline__ ull pack2(float v) {
    ull r; asm("mov.b64 %0, {%1, %1};" : "=l"(r) : "f"(v)); return r;
}
__device__ __forceinline__ ull pack2(float a, float b) {
    ull r; asm("mov.b64 %0, {%1, %2};" : "=l"(r) : "f"(a), "f"(b)); return r;
}
__device__ __forceinline__ float2 unpack2(ull v) {
    float2 f; asm("mov.b64 {%0, %1}, %2;" : "=f"(f.x), "=f"(f.y) : "l"(v)); return f;
}

// -------- scratch (device globals; no allocations allowed) --------
__device__ float g_z   [Bk * BNk * HWk];   // down-proj output (NCHW)
__device__ float g_z2  [Bk * HWk * BNk];   // down-proj output (NHWC) for gather
__device__ float g_d   [Bk * BNk * HWk];   // deform-conv output (NCHW)
__device__ float g_off [Bk * 18  * HWk];   // offsets
__device__ float g_mask[Bk * 9   * HWk];   // sigmoid(mask)
__device__ float g_dwT [Ck * BNk];         // down_w transposed: [c][o]
__device__ float g_uwT [BNk * Ck];         // up_w transposed: [c][oc]
__device__ float g_wbT [BNk * 9 * 32];     // off/mask weights: [(ic*9+tap)*32 + oc]
__device__ float g_wbBias[32];             // 18 off_b + 9 mask_b + pad
__device__ float g_wdT [9 * BNk * BNk];    // def_w: [(k*64+c)*64 + o]
__device__ float g_sum [Ck];
__device__ float g_sumsq[Ck];

// -------- prep: transpose/repack weights, zero stats --------
__global__ void prep_kernel(const float* __restrict__ down_w,
                            const float* __restrict__ off_w,
                            const float* __restrict__ off_b,
                            const float* __restrict__ mask_w,
                            const float* __restrict__ mask_b,
                            const float* __restrict__ def_w,
                            const float* __restrict__ up_w) {
    int i = blockIdx.x * 256 + threadIdx.x;
    if (i < Ck) { g_sum[i] = 0.f; g_sumsq[i] = 0.f; }
    if (i < Ck * BNk) {                 // down_w [64][256] -> [c][o]
        int o = i >> 8, c = i & 255;
        g_dwT[c * 64 + o] = down_w[i];
        // up_w [256][64] -> [c][oc]
        int oc = i >> 6, cc = i & 63;
        g_uwT[cc * 256 + oc] = up_w[i];
    }
    if (i < BNk * 9 * 32) {             // off/mask weights
        int oc = i & 31; int rest = i >> 5;
        int tap = rest % 9, ic = rest / 9;
        float v = 0.f;
        if (oc < 18)      v = off_w [(oc * 64 + ic) * 9 + tap];
        else if (oc < 27) v = mask_w[((oc - 18) * 64 + ic) * 9 + tap];
        g_wbT[i] = v;
    }
    if (i < 32) {
        float v = 0.f;
        if (i < 18)      v = off_b[i];
        else if (i < 27) v = mask_b[i - 18];
        g_wbBias[i] = v;
    }
    if (i < BNk * BNk * 9) {            // def_w [o][c][k] -> [(k*64+c)*64+o]
        int o = i / 576, rem = i % 576, c = rem / 9, k = rem % 9;
        g_wdT[(k * 64 + c) * 64 + o] = def_w[i];
    }
}

// 16 FFMA2: 4 px (dup-pairs) x 8 oc (pairs) -- proven R14 core
#define GEMM16(A, wa, wb, vp0, vp1, vp2, vp3)                     \
    ffma2(A[0][0], wa.x, vp0); ffma2(A[0][1], wa.y, vp0);         \
    ffma2(A[0][2], wb.x, vp0); ffma2(A[0][3], wb.y, vp0);         \
    ffma2(A[1][0], wa.x, vp1); ffma2(A[1][1], wa.y, vp1);         \
    ffma2(A[1][2], wb.x, vp1); ffma2(A[1][3], wb.y, vp1);         \
    ffma2(A[2][0], wa.x, vp2); ffma2(A[2][1], wa.y, vp2);         \
    ffma2(A[2][2], wb.x, vp2); ffma2(A[2][3], wb.y, vp2);         \
    ffma2(A[3][0], wa.x, vp3); ffma2(A[3][1], wa.y, vp3);         \
    ffma2(A[3][2], wb.x, vp3); ffma2(A[3][3], wb.y, vp3);

// -------- kernel A: 1x1 down conv (256->64), 4px x 8oc register tile --------
__global__ void __launch_bounds__(256, 4) down_kernel(const float* __restrict__ x) {
    __shared__ __align__(16) float wsm[64 * 64];    // 16KB: 64-c chunk of dwT
    __shared__ __align__(16) float xsm[64][128];    // 32KB: x tile
    int tid = threadIdx.x;
    int og  = tid >> 5;                // oc group: 8 channels [og*8, og*8+8)
    int q   = tid & 31;                // pixel lane: px {q, q+32, q+64, q+96}
    int bp  = blockIdx.x * 128;
    int b   = bp >> 14;
    int p0  = bp & 16383;

    ull acc2[4][4];
#pragma unroll
    for (int j = 0; j < 4; j++)
#pragma unroll
        for (int o2 = 0; o2 < 4; o2++) acc2[j][o2] = 0ull;

    const float* xb = x + (size_t)b * Ck * HWk + p0;

    for (int c0 = 0; c0 < Ck; c0 += 64) {
        __syncthreads();
        {   // stage weights: 1024 float4
            const float4* wsrc = reinterpret_cast<const float4*>(g_dwT + c0 * 64);
            float4* wdst = reinterpret_cast<float4*>(wsm);
#pragma unroll
            for (int j = tid; j < 1024; j += 256) wdst[j] = wsrc[j];
        }
        {   // stage x tile: 64 ch x 128 px = 2048 float4
            float4* xd = reinterpret_cast<float4*>(&xsm[0][0]);
#pragma unroll
            for (int j = tid; j < 2048; j += 256) {
                int c = j >> 5, x4 = j & 31;
                xd[j] = *reinterpret_cast<const float4*>(xb + (size_t)(c0 + c) * HWk + x4 * 4);
            }
        }
        __syncthreads();

#pragma unroll 2
        for (int ci = 0; ci < 64; ci++) {
            ull vp0 = pack2(xsm[ci][q]);
            ull vp1 = pack2(xsm[ci][q + 32]);
            ull vp2 = pack2(xsm[ci][q + 64]);
            ull vp3 = pack2(xsm[ci][q + 96]);
            const ulonglong2* wp = reinterpret_cast<const ulonglong2*>(wsm + ci * 64 + og * 8);
            ulonglong2 wa = wp[0], wb = wp[1];
            GEMM16(acc2, wa, wb, vp0, vp1, vp2, vp3);
        }
    }

    float* zb  = g_z  + (size_t)b * BNk * HWk + p0;
    float* z2b = g_z2 + ((size_t)b * HWk + p0) * 64;
#pragma unroll
    for (int j = 0; j < 4; j++) {
        int p = q + 32 * j;
#pragma unroll
        for (int o2 = 0; o2 < 4; o2++) {
            float2 f = unpack2(acc2[j][o2]);
            zb[(size_t)(og * 8 + 2 * o2)     * HWk + p] = f.x;
            zb[(size_t)(og * 8 + 2 * o2 + 1) * HWk + p] = f.y;
            *reinterpret_cast<float2*>(z2b + (size_t)p * 64 + og * 8 + 2 * o2) = f;
        }
    }
}

// -------- kernel B: 3x3 conv -> offsets(18) + sigmoid(mask)(9), f32x2 -------
__global__ void __launch_bounds__(256) offmask_kernel() {
    __shared__ __align__(16) float zs[8][4][132];   // halo: 8 ic x 4 rows
    __shared__ __align__(16) float wsm[8 * 9 * 32]; // weights chunk
    int tid = threadIdx.x;
    int r0  = tid >> 7;         // 0/1: which output row
    int tx  = tid & 127;        // x coordinate
    int by  = blockIdx.x;       // row pair
    int b   = blockIdx.y;
    int y   = by * 2 + r0;

    ull acc2[14];
#pragma unroll
    for (int j = 0; j < 14; j++) acc2[j] = pack2(g_wbBias[2 * j], g_wbBias[2 * j + 1]);

    const float* zb = g_z + (size_t)b * BNk * HWk;

#pragma unroll 1
    for (int ic0 = 0; ic0 < 64; ic0 += 8) {
        __syncthreads();
        const float4* wsrc = reinterpret_cast<const float4*>(g_wbT + ic0 * 9 * 32);
        float4* wdst = reinterpret_cast<float4*>(wsm);
#pragma unroll
        for (int j = tid; j < 576; j += 256) wdst[j] = wsrc[j];
#pragma unroll
        for (int j = tid; j < 8 * 4 * 128; j += 256) {
            int ic = j >> 9;
            int r  = (j >> 7) & 3;
            int xx = j & 127;
            int yy = by * 2 + r - 1;
            zs[ic][r][xx + 1] = (yy >= 0 && yy < Hk)
                ? __ldg(zb + (size_t)(ic0 + ic) * HWk + yy * Wk + xx) : 0.f;
        }
        if (tid < 32) {
            int ic = tid >> 2, r = tid & 3;
            zs[ic][r][0] = 0.f; zs[ic][r][129] = 0.f;
        }
        __syncthreads();

#pragma unroll 1
        for (int ic = 0; ic < 8; ic++) {
#pragma unroll
            for (int tap = 0; tap < 9; tap++) {
                int ky = tap / 3, kx = tap % 3;
                ull zp = pack2(zs[ic][r0 + ky][tx + kx]);
                const ulonglong2* w2 = reinterpret_cast<const ulonglong2*>(wsm + (ic * 9 + tap) * 32);
                ulonglong2 wA = w2[0], wB = w2[1], wC = w2[2], wD = w2[3];
                ulonglong2 wE = w2[4], wF = w2[5], wG = w2[6];
                ffma2(acc2[0],  wA.x, zp); ffma2(acc2[1],  wA.y, zp);
                ffma2(acc2[2],  wB.x, zp); ffma2(acc2[3],  wB.y, zp);
                ffma2(acc2[4],  wC.x, zp); ffma2(acc2[5],  wC.y, zp);
                ffma2(acc2[6],  wD.x, zp); ffma2(acc2[7],  wD.y, zp);
                ffma2(acc2[8],  wE.x, zp); ffma2(acc2[9],  wE.y, zp);
                ffma2(acc2[10], wF.x, zp); ffma2(acc2[11], wF.y, zp);
                ffma2(acc2[12], wG.x, zp); ffma2(acc2[13], wG.y, zp);
            }
        }
    }

    int p = y * Wk + tx;
    float* offp = g_off + (size_t)b * 18 * HWk + p;
#pragma unroll
    for (int j = 0; j < 9; j++) {
        float2 f = unpack2(acc2[j]);
        offp[(size_t)(2 * j)     * HWk] = f.x;
        offp[(size_t)(2 * j + 1) * HWk] = f.y;
    }
    float* mp = g_mask + (size_t)b * 9 * HWk + p;
#pragma unroll
    for (int j = 9; j < 14; j++) {
        float2 f = unpack2(acc2[j]);
        int m = 2 * j - 18;
        mp[(size_t)m * HWk] = 1.f / (1.f + __expf(-f.x));
        if (m + 1 < 9) mp[(size_t)(m + 1) * HWk] = 1.f / (1.f + __expf(-f.y));
    }
}

// -------- kernel C: deform conv, NHWC vectorized gather + R14 GEMM ----------
__global__ void __launch_bounds__(256, 4) deform_kernel(const float* __restrict__ def_b) {
    __shared__ __align__(16) float wsm[64 * 64];    // 16KB: wd[k] chunk
    __shared__ __align__(16) float vsm[64][128];    // 32KB: sampled values
    int tid  = threadIdx.x;
    int half = tid >> 7;        // gather role: channel half
    int tx   = tid & 127;       // gather pixel
    int og   = tid >> 5;        // GEMM role: 8 oc
    int q    = tid & 31;        // GEMM pixel lane
    int bp   = blockIdx.x * 128;
    int b    = bp >> 14;
    int p0   = bp & 16383;
    int gy   = (p0 + tx) >> 7;
    int gx   = (p0 + tx) & 127;

    const float* z2b  = g_z2   + (size_t)b * HWk * 64;
    const float* offp = g_off  + (size_t)b * 18  * HWk + p0 + tx;
    const float* mp   = g_mask + (size_t)b * 9   * HWk + p0 + tx;

    ull acc2[4][4];
#pragma unroll
    for (int o2 = 0; o2 < 4; o2++) {
        ull bb = pack2(__ldg(def_b + og * 8 + 2 * o2), __ldg(def_b + og * 8 + 2 * o2 + 1));
#pragma unroll
        for (int j = 0; j < 4; j++) acc2[j][o2] = bb;
    }

#pragma unroll 1
    for (int k = 0; k < 9; k++) {
        __syncthreads();   // previous tap's GEMM done before overwriting smem
        {   // stage this tap's weights
            const float4* wk4 = reinterpret_cast<const float4*>(g_wdT + k * 4096);
            float4* wdst = reinterpret_cast<float4*>(wsm);
#pragma unroll
            for (int j = tid; j < 1024; j += 256) wdst[j] = wk4[j];
        }

        // bilinear gather via NHWC float4 loads: 32 channels per thread
        {
            int ky = k / 3, kx = k % 3;
            float dy = __ldg(offp + (size_t)(2 * k)     * HWk);
            float dx = __ldg(offp + (size_t)(2 * k + 1) * HWk);
            float mk = __ldg(mp   + (size_t)k           * HWk);

            float py = dy + (float)(gy + ky - 1);
            float px = dx + (float)(gx + kx - 1);
            float y0f = floorf(py), x0f = floorf(px);
            float wy = py - y0f, wx = px - x0f;
            int y0 = (int)y0f, x0 = (int)x0f;
            int y1 = y0 + 1,   x1 = x0 + 1;
            bool vy0 = (y0 >= 0) && (y0 < Hk), vy1 = (y1 >= 0) && (y1 < Hk);
            bool vx0 = (x0 >= 0) && (x0 < Wk), vx1 = (x1 >= 0) && (x1 < Wk);
            float a00 = (1.f - wy) * (1.f - wx) * mk * ((vy0 && vx0) ? 1.f : 0.f);
            float a01 = (1.f - wy) * wx         * mk * ((vy0 && vx1) ? 1.f : 0.f);
            float a10 = wy         * (1.f - wx) * mk * ((vy1 && vx0) ? 1.f : 0.f);
            float a11 = wy         * wx         * mk * ((vy1 && vx1) ? 1.f : 0.f);
            int yc0 = min(max(y0, 0), Hk - 1), yc1 = min(max(y1, 0), Hk - 1);
            int xc0 = min(max(x0, 0), Wk - 1), xc1 = min(max(x1, 0), Wk - 1);
            const float4* r00 = reinterpret_cast<const float4*>(z2b + (size_t)(yc0 * Wk + xc0) * 64 + half * 32);
            const float4* r01 = reinterpret_cast<const float4*>(z2b + (size_t)(yc0 * Wk + xc1) * 64 + half * 32);
            const float4* r10 = reinterpret_cast<const float4*>(z2b + (size_t)(yc1 * Wk + xc0) * 64 + half * 32);
            const float4* r11 = reinterpret_cast<const float4*>(z2b + (size_t)(yc1 * Wk + xc1) * 64 + half * 32);

#pragma unroll
            for (int c4 = 0; c4 < 8; c4++) {
                float4 v00 = __ldg(r00 + c4);
                float4 v01 = __ldg(r01 + c4);
                float4 v10 = __ldg(r10 + c4);
                float4 v11 = __ldg(r11 + c4);
                int c = half * 32 + c4 * 4;
                vsm[c + 0][tx] = a00 * v00.x + a01 * v01.x + a10 * v10.x + a11 * v11.x;
                vsm[c + 1][tx] = a00 * v00.y + a01 * v01.y + a10 * v10.y + a11 * v11.y;
                vsm[c + 2][tx] = a00 * v00.z + a01 * v01.z + a10 * v10.z + a11 * v11.z;
                vsm[c + 3][tx] = a00 * v00.w + a01 * v01.w + a10 * v10.w + a11 * v11.w;
            }
        }
        __syncthreads();

        // GEMM: 64 c-steps, each thread 4 px x 8 oc via FFMA2 (R14 core)
#pragma unroll 2
        for (int c = 0; c < 64; c++) {
            ull vp0 = pack2(vsm[c][q]);
            ull vp1 = pack2(vsm[c][q + 32]);
            ull vp2 = pack2(vsm[c][q + 64]);
            ull vp3 = pack2(vsm[c][q + 96]);
            const ulonglong2* wp = reinterpret_cast<const ulonglong2*>(wsm + c * 64 + og * 8);
            ulonglong2 wa = wp[0], wb = wp[1];
            GEMM16(acc2, wa, wb, vp0, vp1, vp2, vp3);
        }
    }

    float* dbp = g_d + (size_t)b * BNk * HWk + p0;
#pragma unroll
    for (int j = 0; j < 4; j++) {
        int p = q + 32 * j;
#pragma unroll
        for (int o2 = 0; o2 < 4; o2++) {
            float2 f = unpack2(acc2[j][o2]);
            dbp[(size_t)(og * 8 + 2 * o2)     * HWk + p] = f.x;
            dbp[(size_t)(og * 8 + 2 * o2 + 1) * HWk + p] = f.y;
        }
    }
}

// -------- kernel D: 1x1 up conv + residual + BN stats, 4px x 8oc tile -------
__global__ void __launch_bounds__(256, 4) up_kernel(const float* __restrict__ x,
                                                    float* __restrict__ out) {
    __shared__ __align__(16) float wsm[64 * 64];   // 16KB: uwT chunk [c][64 oc]
    __shared__ __align__(16) float dsm[64][128];   // 32KB: d tile
    int tid = threadIdx.x;
    int og  = tid >> 5;
    int q   = tid & 31;
    int oh  = blockIdx.y;             // oc quarter: [oh*64, oh*64+64)
    int bp  = blockIdx.x * 128;
    int b   = bp >> 14;
    int p0  = bp & 16383;

    {   // stage weights: wsm[c][oi] = g_uwT[c*256 + oh*64 + oi]
        const float4* usrc = reinterpret_cast<const float4*>(g_uwT);
        float4* wdst = reinterpret_cast<float4*>(wsm);
#pragma unroll
        for (int j = tid; j < 1024; j += 256) {
            int c = j >> 4, o4 = j & 15;
            wdst[j] = usrc[c * 64 + oh * 16 + o4];
        }
    }
    {   // stage d tile
        const float* db = g_d + (size_t)b * BNk * HWk + p0;
        float4* dd = reinterpret_cast<float4*>(&dsm[0][0]);
#pragma unroll
        for (int j = tid; j < 2048; j += 256) {
            int c = j >> 5, x4 = j & 31;
            dd[j] = *reinterpret_cast<const float4*>(db + (size_t)c * HWk + x4 * 4);
        }
    }
    __syncthreads();

    ull acc2[4][4];
#pragma unroll
    for (int j = 0; j < 4; j++)
#pragma unroll
        for (int o2 = 0; o2 < 4; o2++) acc2[j][o2] = 0ull;

#pragma unroll 2
    for (int c = 0; c < 64; c++) {
        ull vp0 = pack2(dsm[c][q]);
        ull vp1 = pack2(dsm[c][q + 32]);
        ull vp2 = pack2(dsm[c][q + 64]);
        ull vp3 = pack2(dsm[c][q + 96]);
        const ulonglong2* wp = reinterpret_cast<const ulonglong2*>(wsm + c * 64 + og * 8);
        ulonglong2 wa = wp[0], wb = wp[1];
        GEMM16(acc2, wa, wb, vp0, vp1, vp2, vp3);
    }

    // epilogue: +x, write, BN partial sums (warp covers all 128 px of block)
    const float* xb = x   + (size_t)b * Ck * HWk + p0;
    float*       ob = out + (size_t)b * Ck * HWk + p0;
#pragma unroll
    for (int o2 = 0; o2 < 4; o2++) {
        int oc0 = oh * 64 + og * 8 + 2 * o2;
        float ws0 = 0.f, wq0 = 0.f, ws1 = 0.f, wq1 = 0.f;
#pragma unroll
        for (int j = 0; j < 4; j++) {
            int p = q + 32 * j;
            float2 f = unpack2(acc2[j][o2]);
            float y0 = __ldg(xb + (size_t)oc0 * HWk + p) + f.x;
            float y1 = __ldg(xb + (size_t)(oc0 + 1) * HWk + p) + f.y;
            ob[(size_t)oc0       * HWk + p] = y0;
            ob[(size_t)(oc0 + 1) * HWk + p] = y1;
            ws0 += y0; wq0 += y0 * y0;
            ws1 += y1; wq1 += y1 * y1;
        }
#pragma unroll
        for (int d = 16; d; d >>= 1) {
            ws0 += __shfl_xor_sync(0xffffffffu, ws0, d);
            wq0 += __shfl_xor_sync(0xffffffffu, wq0, d);
            ws1 += __shfl_xor_sync(0xffffffffu, ws1, d);
            wq1 += __shfl_xor_sync(0xffffffffu, wq1, d);
        }
        if (q == 0) {
            atomicAdd(&g_sum[oc0],       ws0);
            atomicAdd(&g_sumsq[oc0],     wq0);
            atomicAdd(&g_sum[oc0 + 1],   ws1);
            atomicAdd(&g_sumsq[oc0 + 1], wq1);
        }
    }
}

// -------- kernel E: BatchNorm (training stats) + SiLU, in place --------
__global__ void __launch_bounds__(256) norm_kernel(float* __restrict__ out,
                                                   const float* __restrict__ gamma,
                                                   const float* __restrict__ beta) {
    const float invN = 1.f / (float)(Bk * HWk);   // 1/65536
    size_t i = (size_t)blockIdx.x * 256 + threadIdx.x;   // float4 index
    int ch = (int)((i >> 12) & 255);                      // 4096 float4 per channel

    float mean = g_sum[ch] * invN;
    float var  = g_sumsq[ch] * invN - mean * mean;
    float r    = rsqrtf(var + 1e-5f);
    float sc   = r * __ldg(gamma + ch);
    float sh   = __ldg(beta + ch) - mean * sc;

    float4* o4 = reinterpret_cast<float4*>(out);
    float4 v = o4[i];
    float h;
    h = v.x * sc + sh; v.x = h / (1.f + __expf(-h));
    h = v.y * sc + sh; v.y = h / (1.f + __expf(-h));
    h = v.z * sc + sh; v.z = h / (1.f + __expf(-h));
    h = v.w * sc + sh; v.w = h / (1.f + __expf(-h));
    o4[i] = v;
}

// -------- launch --------
extern "C" void kernel_launch(void* const* d_in, const int* in_sizes, int n_in,
                              void* d_out, int out_size) {
    const float* x      = (const float*)d_in[0];
    const float* down_w = (const float*)d_in[1];
    const float* off_w  = (const float*)d_in[2];
    const float* off_b  = (const float*)d_in[3];
    const float* mask_w = (const float*)d_in[4];
    const float* mask_b = (const float*)d_in[5];
    const float* def_w  = (const float*)d_in[6];
    const float* def_b  = (const float*)d_in[7];
    const float* up_w   = (const float*)d_in[8];
    const float* gamma  = (const float*)d_in[9];
    const float* beta   = (const float*)d_in[10];
    float* out = (float*)d_out;

    prep_kernel<<<144, 256>>>(down_w, off_w, off_b, mask_w, mask_b, def_w, up_w);
    down_kernel<<<512, 256>>>(x);
    offmask_kernel<<<dim3(Hk / 2, Bk), 256>>>();
    deform_kernel<<<512, 256>>>(def_b);
    up_kernel<<<dim3(512, 4), 256>>>(x, out);
    norm_kernel<<<(Bk * Ck * HWk) / 4 / 256, 256>>>(out, gamma, beta);
}